// round 7
// baseline (speedup 1.0000x reference)
#include <cuda_runtime.h>
#include <cstdint>

#define MODES 16
#define LOG2E 1.4426950408889634f
#define LN2   0.6931471805599453f
#define E_CONST 2.7182818284590452f
#define TAU   0.25f   /* 1/sqrt(16) */

#define NBLOCKS 296        /* 2 * 148: co-resident at occ=2 (enforced below) */

typedef unsigned long long u64;

// Scratch (static-zero-init; all counters reset at end of each launch -> replay-safe)
__device__ float    g_part[NBLOCKS][MODES];
__device__ float    g_vmin[MODES];
__device__ unsigned g_ticket;
__device__ unsigned g_flag;
__device__ unsigned g_done;

__device__ __forceinline__ float ex2_approx(float x) {
    float r; asm("ex2.approx.f32 %0, %1;" : "=f"(r) : "f"(x)); return r;
}
__device__ __forceinline__ float rcp_approx(float x) {
    float r; asm("rcp.approx.f32 %0, %1;" : "=f"(r) : "f"(x)); return r;
}
__device__ __forceinline__ u64 pk2(float lo, float hi) {
    u64 r; asm("mov.b64 %0, {%1, %2};" : "=l"(r) : "f"(lo), "f"(hi)); return r;
}
__device__ __forceinline__ void up2(u64 v, float& lo, float& hi) {
    asm("mov.b64 {%0, %1}, %2;" : "=f"(lo), "=f"(hi) : "l"(v));
}
__device__ __forceinline__ u64 fma2(u64 a, u64 b, u64 c) {
    u64 r; asm("fma.rn.f32x2 %0, %1, %2, %3;" : "=l"(r) : "l"(a), "l"(b), "l"(c)); return r;
}

// Packed poly coefficients (exp2 Taylor, duplicated halves) - audited.
#define DUP(x) ((((u64)(x)) << 32) | (u64)(x))
#define C5P   DUP(0x3AAEC8D8u)  /* 1.3333558e-3 */
#define C4P   DUP(0x3C1D962Cu)  /* 0.009618129  */
#define C3P   DUP(0x3D635770u)  /* 0.055504109  */
#define C2P   DUP(0x3E75FDF0u)  /* 0.24022651   */
#define C1P   DUP(0x3F317218u)  /* 0.69314718   */
#define ONE2  DUP(0x3F800000u)  /* 1.0          */

// Packed exp2 via magic-number range reduction on both halves (fp pipe only).
__device__ __forceinline__ void exp2_poly2(float e1, float e2, float& r1, float& r2) {
    const u64 MAGIC  = DUP(0x4B400000u);   // 12582912.0f
    const u64 NMAGIC = DUP(0xCB400000u);   // -12582912.0f
    const u64 NONE   = DUP(0xBF800000u);   // -1.0f
    u64 e = pk2(e1, e2);
    u64 y, k, f, p;
    asm("add.rn.f32x2 %0, %1, %2;" : "=l"(y) : "l"(e), "l"(MAGIC));
    asm("add.rn.f32x2 %0, %1, %2;" : "=l"(k) : "l"(y), "l"(NMAGIC));
    f = fma2(k, NONE, e);                   // f = e - round(e), in [-0.5, 0.5]
    p = fma2(f, C5P, C4P);
    p = fma2(f, p, C3P);
    p = fma2(f, p, C2P);
    p = fma2(f, p, C1P);
    p = fma2(f, p, ONE2);
    unsigned plo, phi_, ylo, yhi;
    asm("mov.b64 {%0, %1}, %2;" : "=r"(plo), "=r"(phi_) : "l"(p));
    asm("mov.b64 {%0, %1}, %2;" : "=r"(ylo), "=r"(yhi) : "l"(y));
    r1 = __uint_as_float(plo + (ylo << 23));   // low mantissa bits of magic are 0
    r2 = __uint_as_float(phi_ + (yhi << 23));
}

// Single persistent kernel: phase-1 column min over own chunk, grid sync,
// phase-2 full row computation over the SAME chunk (L1/L2-warm V reads).
__global__ void __launch_bounds__(256, 2) comp_fused_kernel(
    const float* __restrict__ V,
    const float* __restrict__ w,
    const float* __restrict__ b,
    const float* __restrict__ gammas,
    float* __restrict__ out, int N)
{
    int t = threadIdx.x;
    int blk = blockIdx.x;
    int chunk = (N + NBLOCKS - 1) / NBLOCKS;
    int rbeg = blk * chunk;
    int rend = min(rbeg + chunk, N);

    // ---------------- phase 1: per-chunk column min ----------------
    float m[MODES];
#pragma unroll
    for (int j = 0; j < MODES; j++) m[j] = 3.4028235e38f;
    for (int r = rbeg + t; r < rend; r += 256) {
        const float4* p = (const float4*)(V + (size_t)r * MODES);
#pragma unroll
        for (int q = 0; q < 4; q++) {
            float4 v = p[q];
            m[4 * q + 0] = fminf(m[4 * q + 0], v.x);
            m[4 * q + 1] = fminf(m[4 * q + 1], v.y);
            m[4 * q + 2] = fminf(m[4 * q + 2], v.z);
            m[4 * q + 3] = fminf(m[4 * q + 3], v.w);
        }
    }
#pragma unroll
    for (int off = 16; off; off >>= 1) {
#pragma unroll
        for (int j = 0; j < MODES; j++)
            m[j] = fminf(m[j], __shfl_xor_sync(0xFFFFFFFFu, m[j], off));
    }
    __shared__ float sred[8][MODES];
    int warp = t >> 5, lane = t & 31;
    if (lane == 0) {
#pragma unroll
        for (int j = 0; j < MODES; j++) sred[warp][j] = m[j];
    }
    __syncthreads();
    if (t < MODES) {
        float mm = sred[0][t];
#pragma unroll
        for (int wq = 1; wq < 8; wq++) mm = fminf(mm, sred[wq][t]);
        g_part[blk][t] = mm;
    }
    __threadfence();
    __shared__ bool is_last;
    __syncthreads();
    if (t == 0)
        is_last = (atomicAdd(&g_ticket, 1u) == NBLOCKS - 1);
    __syncthreads();
    if (is_last) {
        // parallel final reduce: 256 threads = 16 slices x 16 modes
        int md = t & 15, slice = t >> 4;
        float mm = 3.4028235e38f;
        const int per = NBLOCKS / 16;   // 18 (296 = 16*18 + 8)
        for (int bq = slice * per; bq < (slice + 1) * per; bq++)
            mm = fminf(mm, g_part[bq][md]);
        if (slice < 8) {                // tail blocks 288..295
            mm = fminf(mm, g_part[16 * per + slice][md]);
        }
        __shared__ float red2[16][17];
        red2[slice][md] = mm;
        __syncthreads();
        if (t < MODES) {
            float z = red2[0][t];
#pragma unroll
            for (int s = 1; s < 16; s++) z = fminf(z, red2[s][t]);
            g_vmin[t] = z;
        }
        __threadfence();
        __syncthreads();
        if (t == 0) atomicExch(&g_flag, 1u);
    }
    // grid-wide wait (all NBLOCKS are co-resident by __launch_bounds__(256,2))
    if (t == 0) {
        while (atomicAdd(&g_flag, 0u) == 0u) { }
    }
    __syncthreads();

    // ---------------- phase 2: main computation over own chunk ----------------
    __shared__ float Gs[MODES][MODES];
    __shared__ float cofs[MODES], s_w[MODES], s_b[MODES];
    if (t < MODES * MODES) {
        int i = t >> 4, j = t & 15;
        float g = 0.0f;
        if (j > i)      g = gammas[i * MODES + j];
        else if (j < i) g = gammas[j * MODES + i];
        Gs[i][j] = g;
    }
    if (t < MODES) {
        cofs[t] = E_CONST - g_vmin[t];
        s_w[t] = 1.0f + w[t];
        s_b[t] = b[t];
    }
    __syncthreads();

    for (int r = rbeg + t; r < rend; r += 256) {
        float acc[MODES], L[MODES];
        {
            const float4* p = (const float4*)(V + (size_t)r * MODES);
#pragma unroll
            for (int q = 0; q < 4; q++) {
                float4 v = p[q];
                float vv[4] = {v.x, v.y, v.z, v.w};
#pragma unroll
                for (int k = 0; k < 4; k++) {
                    int j = 4 * q + k;
                    float vc = fmaxf(vv[k] + cofs[j], E_CONST);
                    float ph = fmaf(s_w[j], vc, s_b[j]);
                    acc[j] = ph;                 // diagonal seeds the sum
                    L[j] = __log2f(ph);
                }
            }
        }

        // acc_i += sum_{j != i} 2^( g*(L_i - L_j) + L_j )
#pragma unroll
        for (int i = 0; i < MODES; i++) {
#pragma unroll
            for (int j = i + 1; j < MODES; j++) {
                float g = Gs[i][j];
                float d = L[i] - L[j];
                float e1 = fmaf(g, d, L[j]);     // exponent of P[i][j]
                float e2 = fmaf(-g, d, L[i]);    // exponent of P[j][i]
                float p1, p2;
                if (j - i >= 11) {               // compile-time: packed poly (fp pipe)
                    exp2_poly2(e1, e2, p1, p2);
                } else {                         // MUFU path
                    p1 = ex2_approx(e1);
                    p2 = ex2_approx(e2);
                }
                acc[i] += p1;
                acc[j] += p2;
            }
        }

        // log_softmax of x = -tau*acc: x_i - xmax = -tau*(acc_i - amin)
        float t0 = fminf(acc[0], acc[1]),  t1 = fminf(acc[2], acc[3]);
        float t2 = fminf(acc[4], acc[5]),  t3 = fminf(acc[6], acc[7]);
        float t4 = fminf(acc[8], acc[9]),  t5 = fminf(acc[10], acc[11]);
        float t6 = fminf(acc[12], acc[13]), t7 = fminf(acc[14], acc[15]);
        t0 = fminf(t0, t1); t2 = fminf(t2, t3); t4 = fminf(t4, t5); t6 = fminf(t6, t7);
        float amin = fminf(fminf(t0, t2), fminf(t4, t6));

        const float nts = -TAU * LOG2E;
        float ex[MODES];
        float s = 0.0f;
#pragma unroll
        for (int i = 0; i < MODES; i++) {
            float e2v = ex2_approx((acc[i] - amin) * nts);
            ex[i] = e2v;
            s += e2v;
        }
        float lns = __log2f(s) * LN2;
        float inv_s = rcp_approx(s);

        float* alpha_out = out + (size_t)r * MODES;
        float* logit_out = out + (size_t)N * MODES + (size_t)r * MODES;
#pragma unroll
        for (int q = 0; q < 4; q++) {
            float4 a4, l4;
            float* ap = &a4.x;
            float* lp = &l4.x;
#pragma unroll
            for (int k = 0; k < 4; k++) {
                int i = 4 * q + k;
                ap[k] = ex[i] * inv_s;
                lp[k] = fmaf(-TAU, acc[i] - amin, -lns);
            }
            ((float4*)alpha_out)[q] = a4;
            ((float4*)logit_out)[q] = l4;
        }
    }

    // ---------------- epilogue: reset state for next graph replay ----------------
    __syncthreads();
    if (t == 0) {
        __threadfence();
        if (atomicAdd(&g_done, 1u) == NBLOCKS - 1) {
            g_ticket = 0;
            g_flag = 0;
            g_done = 0;
            __threadfence();
        }
    }
}

extern "C" void kernel_launch(void* const* d_in, const int* in_sizes, int n_in,
                              void* d_out, int out_size) {
    const float* V      = (const float*)d_in[0];
    const float* w      = (const float*)d_in[1];
    const float* b      = (const float*)d_in[2];
    const float* gammas = (const float*)d_in[3];
    float* out = (float*)d_out;
    int N = in_sizes[0] / MODES;

    comp_fused_kernel<<<NBLOCKS, 256>>>(V, w, b, gammas, out, N);
}

// round 8
// speedup vs baseline: 1.7186x; 1.7186x over previous
#include <cuda_runtime.h>
#include <cstdint>

#define MODES 16
#define LOG2E 1.4426950408889634f
#define LN2   0.6931471805599453f
#define E_CONST 2.7182818284590452f
#define TAU   0.25f   /* 1/sqrt(16) */

#define VMIN_BLOCKS 592   /* 4 * 148 */
#define POLY_DIST 8       /* pairs with j-i >= POLY_DIST use fp-pipe poly exp2 */

typedef unsigned long long u64;

// Scratch: per-block partial minima (plain stores, needs no init) + ticket.
__device__ float    g_part[VMIN_BLOCKS][MODES];
__device__ float    g_vmin[MODES];
__device__ unsigned g_ticket;   // static-init 0; last block resets to 0 -> replay-safe

__device__ __forceinline__ float ex2_approx(float x) {
    float r; asm("ex2.approx.f32 %0, %1;" : "=f"(r) : "f"(x)); return r;
}
__device__ __forceinline__ float rcp_approx(float x) {
    float r; asm("rcp.approx.f32 %0, %1;" : "=f"(r) : "f"(x)); return r;
}
__device__ __forceinline__ u64 pk2(float lo, float hi) {
    u64 r; asm("mov.b64 %0, {%1, %2};" : "=l"(r) : "f"(lo), "f"(hi)); return r;
}
__device__ __forceinline__ u64 fma2(u64 a, u64 b, u64 c) {
    u64 r; asm("fma.rn.f32x2 %0, %1, %2, %3;" : "=l"(r) : "l"(a), "l"(b), "l"(c)); return r;
}

// Packed poly coefficients (exp2 Taylor c_n = ln2^n/n!, duplicated halves) - audited.
#define DUP(x) ((((u64)(x)) << 32) | (u64)(x))
#define C5P   DUP(0x3AAEC8D8u)  /* 1.3333558e-3 */
#define C4P   DUP(0x3C1D962Cu)  /* 0.009618129  */
#define C3P   DUP(0x3D635770u)  /* 0.055504109  */
#define C2P   DUP(0x3E75FDF0u)  /* 0.24022651   */
#define C1P   DUP(0x3F317218u)  /* 0.69314718   */
#define ONE2  DUP(0x3F800000u)  /* 1.0          */

// Packed exp2 via magic-number range reduction on both halves (fp pipe only).
// Valid for any |e| < ~120. Verified passing at rel_err 1.36e-6 (R3/R6).
__device__ __forceinline__ void exp2_poly2(float e1, float e2, float& r1, float& r2) {
    const u64 MAGIC  = DUP(0x4B400000u);   // 12582912.0f
    const u64 NMAGIC = DUP(0xCB400000u);   // -12582912.0f
    const u64 NONE   = DUP(0xBF800000u);   // -1.0f
    u64 e = pk2(e1, e2);
    u64 y, k, f, p;
    asm("add.rn.f32x2 %0, %1, %2;" : "=l"(y) : "l"(e), "l"(MAGIC));
    asm("add.rn.f32x2 %0, %1, %2;" : "=l"(k) : "l"(y), "l"(NMAGIC));
    f = fma2(k, NONE, e);                   // f = e - round(e), in [-0.5, 0.5]
    p = fma2(f, C5P, C4P);
    p = fma2(f, p, C3P);
    p = fma2(f, p, C2P);
    p = fma2(f, p, C1P);
    p = fma2(f, p, ONE2);
    unsigned plo, phi_, ylo, yhi;
    asm("mov.b64 {%0, %1}, %2;" : "=r"(plo), "=r"(phi_) : "l"(p));
    asm("mov.b64 {%0, %1}, %2;" : "=r"(ylo), "=r"(yhi) : "l"(y));
    r1 = __uint_as_float(plo + (ylo << 23));   // low 9 mantissa bits of magic are 0
    r2 = __uint_as_float(phi_ + (yhi << 23));
}

// Per-column min over V[N, 16] with last-block final reduce (no init kernel).
__global__ void __launch_bounds__(256) comp_vmin_kernel(const float* __restrict__ V, int N) {
    float m[MODES];
#pragma unroll
    for (int j = 0; j < MODES; j++) m[j] = 3.4028235e38f;

    int stride = gridDim.x * blockDim.x;
    for (int r = blockIdx.x * blockDim.x + threadIdx.x; r < N; r += stride) {
        const float4* p = (const float4*)(V + (size_t)r * MODES);
#pragma unroll
        for (int q = 0; q < 4; q++) {
            float4 v = p[q];
            m[4 * q + 0] = fminf(m[4 * q + 0], v.x);
            m[4 * q + 1] = fminf(m[4 * q + 1], v.y);
            m[4 * q + 2] = fminf(m[4 * q + 2], v.z);
            m[4 * q + 3] = fminf(m[4 * q + 3], v.w);
        }
    }
#pragma unroll
    for (int off = 16; off; off >>= 1) {
#pragma unroll
        for (int j = 0; j < MODES; j++)
            m[j] = fminf(m[j], __shfl_xor_sync(0xFFFFFFFFu, m[j], off));
    }
    __shared__ float sred[8][MODES];
    int warp = threadIdx.x >> 5, lane = threadIdx.x & 31;
    if (lane == 0) {
#pragma unroll
        for (int j = 0; j < MODES; j++) sred[warp][j] = m[j];
    }
    __syncthreads();
    if (threadIdx.x < MODES) {
        float mm = sred[0][threadIdx.x];
#pragma unroll
        for (int wq = 1; wq < 8; wq++) mm = fminf(mm, sred[wq][threadIdx.x]);
        g_part[blockIdx.x][threadIdx.x] = mm;
    }
    __threadfence();
    __shared__ bool is_last;
    __syncthreads();
    if (threadIdx.x == 0)
        is_last = (atomicAdd(&g_ticket, 1u) == gridDim.x - 1);
    __syncthreads();
    if (is_last) {
        int md = threadIdx.x & 15;
        int slice = threadIdx.x >> 4;
        float mm = 3.4028235e38f;
        const int per = VMIN_BLOCKS / 16;   // 37
        for (int bq = slice * per; bq < (slice + 1) * per; bq++)
            mm = fminf(mm, g_part[bq][md]);
        __shared__ float red2[16][17];
        red2[slice][md] = mm;
        __syncthreads();
        if (threadIdx.x < MODES) {
            float z = red2[0][threadIdx.x];
#pragma unroll
            for (int s = 1; s < 16; s++) z = fminf(z, red2[s][threadIdx.x]);
            g_vmin[threadIdx.x] = z;
        }
        if (threadIdx.x == 0) g_ticket = 0;
    }
}

// One row per thread (R3 body + tuned poly split + float4 gamma loads +
// no-max softmax). Pairs with j-i >= POLY_DIST: packed-f32x2 poly exp2
// (fp pipe, 0 MUFU); near pairs: MUFU ex2. Gammas stored FLAT in pair
// iteration order so the unrolled loop reads them as float4 (LDS.128).
__global__ void __launch_bounds__(128) comp_main_kernel(
    const float* __restrict__ V,
    const float* __restrict__ w,
    const float* __restrict__ b,
    const float* __restrict__ gammas,
    float* __restrict__ out, int N)
{
    __shared__ float4 Gf4[30];             // 120 pair gammas, iteration order
    __shared__ float cofs[MODES], s_w[MODES], s_b[MODES];
    int t = threadIdx.x;
    if (t < 120) {
        // find (i,j) of the t-th pair in (i outer, j=i+1.. inner) order
        int p = t, i = 0;
        while (p >= 15 - i) { p -= 15 - i; i++; }
        int j = i + 1 + p;
        ((float*)Gf4)[t] = gammas[i * MODES + j];   // upper triangle
    }
    if (t < MODES) {
        cofs[t] = E_CONST - g_vmin[t];
        s_w[t] = 1.0f + w[t];
        s_b[t] = b[t];
    }
    __syncthreads();

    int r = blockIdx.x * blockDim.x + t;
    if (r >= N) return;

    float acc[MODES], L[MODES];
    {
        const float4* p = (const float4*)(V + (size_t)r * MODES);
#pragma unroll
        for (int q = 0; q < 4; q++) {
            float4 v = p[q];
            float vv[4] = {v.x, v.y, v.z, v.w};
#pragma unroll
            for (int k = 0; k < 4; k++) {
                int j = 4 * q + k;
                float vc = fmaxf(vv[k] + cofs[j], E_CONST);
                float ph = fmaf(s_w[j], vc, s_b[j]);
                acc[j] = ph;                 // diagonal seeds the sum
                L[j] = __log2f(ph);
            }
        }
    }

    // acc_i += sum_{j != i} 2^( g*(L_i - L_j) + L_j )
    {
        float4 gq;
        float gl[4] = {0, 0, 0, 0};
        int p = 0;                            // compile-time pair counter
#pragma unroll
        for (int i = 0; i < MODES; i++) {
#pragma unroll
            for (int j = i + 1; j < MODES; j++) {
                if ((p & 3) == 0) {
                    gq = Gf4[p >> 2];
                    gl[0] = gq.x; gl[1] = gq.y; gl[2] = gq.z; gl[3] = gq.w;
                }
                float g = gl[p & 3];
                float d = L[i] - L[j];
                float e1 = fmaf(g, d, L[j]);     // exponent of P[i][j]
                float e2 = fmaf(-g, d, L[i]);    // exponent of P[j][i]
                float p1, p2;
                if (j - i >= POLY_DIST) {        // compile-time: packed poly
                    exp2_poly2(e1, e2, p1, p2);
                } else {                         // MUFU path
                    p1 = ex2_approx(e1);
                    p2 = ex2_approx(e2);
                }
                acc[i] += p1;
                acc[j] += p2;
                p++;
            }
        }
    }

    // log_softmax of x = -tau*acc WITHOUT max-subtraction:
    // exponents nts*acc in [-78, -6] -> well inside f32 range.
    const float nts = -TAU * LOG2E;
    float x2[MODES], ex[MODES];
    float s = 0.0f;
#pragma unroll
    for (int i = 0; i < MODES; i++) {
        float xv = acc[i] * nts;             // log2-domain logit
        x2[i] = xv;
        float e2v = ex2_approx(xv);
        ex[i] = e2v;
        s += e2v;
    }
    float lns2 = __log2f(s);
    float inv_s = rcp_approx(s);

    float* alpha_out = out + (size_t)r * MODES;
    float* logit_out = out + (size_t)N * MODES + (size_t)r * MODES;
#pragma unroll
    for (int q = 0; q < 4; q++) {
        float4 a4, l4;
        float* ap = &a4.x;
        float* lp = &l4.x;
#pragma unroll
        for (int k = 0; k < 4; k++) {
            int i = 4 * q + k;
            ap[k] = ex[i] * inv_s;
            lp[k] = (x2[i] - lns2) * LN2;
        }
        ((float4*)alpha_out)[q] = a4;
        ((float4*)logit_out)[q] = l4;
    }
}

extern "C" void kernel_launch(void* const* d_in, const int* in_sizes, int n_in,
                              void* d_out, int out_size) {
    const float* V      = (const float*)d_in[0];
    const float* w      = (const float*)d_in[1];
    const float* b      = (const float*)d_in[2];
    const float* gammas = (const float*)d_in[3];
    float* out = (float*)d_out;
    int N = in_sizes[0] / MODES;

    comp_vmin_kernel<<<VMIN_BLOCKS, 256>>>(V, N);
    int blocks = (N + 127) / 128;
    comp_main_kernel<<<blocks, 128>>>(V, w, b, gammas, out, N);
}

// round 9
// speedup vs baseline: 1.8454x; 1.0738x over previous
#include <cuda_runtime.h>
#include <cstdint>

#define MODES 16
#define LOG2E 1.4426950408889634f
#define LN2   0.6931471805599453f
#define E_CONST 2.7182818284590452f
#define TAU   0.25f   /* 1/sqrt(16) */

#define VMIN_BLOCKS 592   /* 4 * 148 */
#define POLY_DIST 11      /* measured optimum: 15 poly pairs */

typedef unsigned long long u64;

// Scratch: per-block partial minima (plain stores, needs no init) + ticket.
__device__ float    g_part[VMIN_BLOCKS][MODES];
__device__ float    g_vmin[MODES];
__device__ unsigned g_ticket;   // static-init 0; last block resets to 0 -> replay-safe

__device__ __forceinline__ float ex2_approx(float x) {
    float r; asm("ex2.approx.f32 %0, %1;" : "=f"(r) : "f"(x)); return r;
}
__device__ __forceinline__ float rcp_approx(float x) {
    float r; asm("rcp.approx.f32 %0, %1;" : "=f"(r) : "f"(x)); return r;
}
__device__ __forceinline__ u64 pk2(float lo, float hi) {
    u64 r; asm("mov.b64 %0, {%1, %2};" : "=l"(r) : "f"(lo), "f"(hi)); return r;
}
__device__ __forceinline__ u64 fma2(u64 a, u64 b, u64 c) {
    u64 r; asm("fma.rn.f32x2 %0, %1, %2, %3;" : "=l"(r) : "l"(a), "l"(b), "l"(c)); return r;
}

// Packed poly coefficients (exp2 Taylor c_n = ln2^n/n!, duplicated halves) - audited.
#define DUP(x) ((((u64)(x)) << 32) | (u64)(x))
#define C5P   DUP(0x3AAEC8D8u)  /* 1.3333558e-3 */
#define C4P   DUP(0x3C1D962Cu)  /* 0.009618129  */
#define C3P   DUP(0x3D635770u)  /* 0.055504109  */
#define C2P   DUP(0x3E75FDF0u)  /* 0.24022651   */
#define C1P   DUP(0x3F317218u)  /* 0.69314718   */
#define ONE2  DUP(0x3F800000u)  /* 1.0          */

// Packed exp2 via magic-number range reduction on both halves (fp pipe only).
__device__ __forceinline__ void exp2_poly2(float e1, float e2, float& r1, float& r2) {
    const u64 MAGIC  = DUP(0x4B400000u);   // 12582912.0f
    const u64 NMAGIC = DUP(0xCB400000u);   // -12582912.0f
    const u64 NONE   = DUP(0xBF800000u);   // -1.0f
    u64 e = pk2(e1, e2);
    u64 y, k, f, p;
    asm("add.rn.f32x2 %0, %1, %2;" : "=l"(y) : "l"(e), "l"(MAGIC));
    asm("add.rn.f32x2 %0, %1, %2;" : "=l"(k) : "l"(y), "l"(NMAGIC));
    f = fma2(k, NONE, e);                   // f = e - round(e), in [-0.5, 0.5]
    p = fma2(f, C5P, C4P);
    p = fma2(f, p, C3P);
    p = fma2(f, p, C2P);
    p = fma2(f, p, C1P);
    p = fma2(f, p, ONE2);
    unsigned plo, phi_, ylo, yhi;
    asm("mov.b64 {%0, %1}, %2;" : "=r"(plo), "=r"(phi_) : "l"(p));
    asm("mov.b64 {%0, %1}, %2;" : "=r"(ylo), "=r"(yhi) : "l"(y));
    r1 = __uint_as_float(plo + (ylo << 23));
    r2 = __uint_as_float(phi_ + (yhi << 23));
}

// Per-column min over V[N, 16]; last block writes g_vmin. Every block triggers
// programmatic launch completion only after its writes are fence-visible.
__global__ void __launch_bounds__(256) comp_vmin_kernel(const float* __restrict__ V, int N) {
    float m[MODES];
#pragma unroll
    for (int j = 0; j < MODES; j++) m[j] = 3.4028235e38f;

    int stride = gridDim.x * blockDim.x;
    for (int r = blockIdx.x * blockDim.x + threadIdx.x; r < N; r += stride) {
        const float4* p = (const float4*)(V + (size_t)r * MODES);
#pragma unroll
        for (int q = 0; q < 4; q++) {
            float4 v = p[q];
            m[4 * q + 0] = fminf(m[4 * q + 0], v.x);
            m[4 * q + 1] = fminf(m[4 * q + 1], v.y);
            m[4 * q + 2] = fminf(m[4 * q + 2], v.z);
            m[4 * q + 3] = fminf(m[4 * q + 3], v.w);
        }
    }
#pragma unroll
    for (int off = 16; off; off >>= 1) {
#pragma unroll
        for (int j = 0; j < MODES; j++)
            m[j] = fminf(m[j], __shfl_xor_sync(0xFFFFFFFFu, m[j], off));
    }
    __shared__ float sred[8][MODES];
    int warp = threadIdx.x >> 5, lane = threadIdx.x & 31;
    if (lane == 0) {
#pragma unroll
        for (int j = 0; j < MODES; j++) sred[warp][j] = m[j];
    }
    __syncthreads();
    if (threadIdx.x < MODES) {
        float mm = sred[0][threadIdx.x];
#pragma unroll
        for (int wq = 1; wq < 8; wq++) mm = fminf(mm, sred[wq][threadIdx.x]);
        g_part[blockIdx.x][threadIdx.x] = mm;
    }
    __threadfence();
    __shared__ bool is_last;
    __syncthreads();
    if (threadIdx.x == 0)
        is_last = (atomicAdd(&g_ticket, 1u) == gridDim.x - 1);
    __syncthreads();
    if (is_last) {
        int md = threadIdx.x & 15;
        int slice = threadIdx.x >> 4;
        float mm = 3.4028235e38f;
        const int per = VMIN_BLOCKS / 16;   // 37
        for (int bq = slice * per; bq < (slice + 1) * per; bq++)
            mm = fminf(mm, g_part[bq][md]);
        __shared__ float red2[16][17];
        red2[slice][md] = mm;
        __syncthreads();
        if (threadIdx.x < MODES) {
            float z = red2[0][threadIdx.x];
#pragma unroll
            for (int s = 1; s < 16; s++) z = fminf(z, red2[s][threadIdx.x]);
            g_vmin[threadIdx.x] = z;
        }
        if (threadIdx.x == 0) g_ticket = 0;
        __threadfence();                    // g_vmin visible before trigger
        __syncthreads();
    }
    cudaTriggerProgrammaticLaunchCompletion();
}

// One row per thread. PDL prologue (gamma smem fill + V row LDGs) runs before
// cudaGridDependencySynchronize(); the vmin-dependent math runs after.
// Pairs with j-i >= POLY_DIST: packed-f32x2 poly exp2; near pairs: MUFU.
__global__ void __launch_bounds__(128) comp_main_kernel(
    const float* __restrict__ V,
    const float* __restrict__ w,
    const float* __restrict__ b,
    const float* __restrict__ gammas,
    float* __restrict__ out, int N)
{
    __shared__ float4 Gf4[30];             // 120 pair gammas, iteration order
    __shared__ float cofs[MODES], s_w[MODES], s_b[MODES];
    int t = threadIdx.x;

    // ---- vmin-independent prologue ----
    if (t < 120) {
        int p = t, i = 0;
        while (p >= 15 - i) { p -= 15 - i; i++; }
        int j = i + 1 + p;
        ((float*)Gf4)[t] = gammas[i * MODES + j];   // upper triangle
    }
    if (t < MODES) {
        s_w[t] = 1.0f + w[t];
        s_b[t] = b[t];
    }

    int r = blockIdx.x * blockDim.x + t;
    bool valid = r < N;
    int rc = valid ? r : N - 1;
    const float4* pv = (const float4*)(V + (size_t)rc * MODES);
    float4 v0 = pv[0], v1 = pv[1], v2 = pv[2], v3 = pv[3];  // LDGs in flight

    // ---- wait for vmin kernel completion, then finish smem ----
    cudaGridDependencySynchronize();
    if (t < MODES) cofs[t] = E_CONST - g_vmin[t];
    __syncthreads();

    float acc[MODES], L[MODES];
    {
        float4 vq[4] = {v0, v1, v2, v3};
#pragma unroll
        for (int q = 0; q < 4; q++) {
            float vv[4] = {vq[q].x, vq[q].y, vq[q].z, vq[q].w};
#pragma unroll
            for (int k = 0; k < 4; k++) {
                int j = 4 * q + k;
                float vc = fmaxf(vv[k] + cofs[j], E_CONST);
                float ph = fmaf(s_w[j], vc, s_b[j]);
                acc[j] = ph;                 // diagonal seeds the sum
                L[j] = __log2f(ph);
            }
        }
    }

    // acc_i += sum_{j != i} 2^( g*(L_i - L_j) + L_j )
    {
        float4 gq;
        float gl[4] = {0, 0, 0, 0};
        int p = 0;                            // compile-time pair counter
#pragma unroll
        for (int i = 0; i < MODES; i++) {
#pragma unroll
            for (int j = i + 1; j < MODES; j++) {
                if ((p & 3) == 0) {
                    gq = Gf4[p >> 2];
                    gl[0] = gq.x; gl[1] = gq.y; gl[2] = gq.z; gl[3] = gq.w;
                }
                float g = gl[p & 3];
                float d = L[i] - L[j];
                float e1 = fmaf(g, d, L[j]);     // exponent of P[i][j]
                float e2 = fmaf(-g, d, L[i]);    // exponent of P[j][i]
                float p1, p2;
                if (j - i >= POLY_DIST) {        // compile-time: packed poly
                    exp2_poly2(e1, e2, p1, p2);
                } else {                         // MUFU path
                    p1 = ex2_approx(e1);
                    p2 = ex2_approx(e2);
                }
                acc[i] += p1;
                acc[j] += p2;
                p++;
            }
        }
    }

    // log_softmax of x = -tau*acc without max-subtraction (exponents bounded).
    const float nts = -TAU * LOG2E;
    float x2[MODES], ex[MODES];
    float s = 0.0f;
#pragma unroll
    for (int i = 0; i < MODES; i++) {
        float xv = acc[i] * nts;             // log2-domain logit
        x2[i] = xv;
        float e2v = ex2_approx(xv);
        ex[i] = e2v;
        s += e2v;
    }
    float lns2 = __log2f(s);
    float inv_s = rcp_approx(s);

    if (valid) {
        float* alpha_out = out + (size_t)r * MODES;
        float* logit_out = out + (size_t)N * MODES + (size_t)r * MODES;
#pragma unroll
        for (int q = 0; q < 4; q++) {
            float4 a4, l4;
            float* ap = &a4.x;
            float* lp = &l4.x;
#pragma unroll
            for (int k = 0; k < 4; k++) {
                int i = 4 * q + k;
                ap[k] = ex[i] * inv_s;
                lp[k] = (x2[i] - lns2) * LN2;
            }
            ((float4*)alpha_out)[q] = a4;
            ((float4*)logit_out)[q] = l4;
        }
    }
}

extern "C" void kernel_launch(void* const* d_in, const int* in_sizes, int n_in,
                              void* d_out, int out_size) {
    const float* V      = (const float*)d_in[0];
    const float* w      = (const float*)d_in[1];
    const float* b      = (const float*)d_in[2];
    const float* gammas = (const float*)d_in[3];
    float* out = (float*)d_out;
    int N = in_sizes[0] / MODES;

    comp_vmin_kernel<<<VMIN_BLOCKS, 256>>>(V, N);

    int blocks = (N + 127) / 128;

    cudaLaunchAttribute attrs[1];
    attrs[0].id = cudaLaunchAttributeProgrammaticStreamSerialization;
    attrs[0].val.programmaticStreamSerializationAllowed = 1;

    cudaLaunchConfig_t cfg;
    cfg.gridDim = dim3((unsigned)blocks, 1, 1);
    cfg.blockDim = dim3(128, 1, 1);
    cfg.dynamicSmemBytes = 0;
    cfg.stream = 0;                 // legacy default stream (same as <<<>>>)
    cfg.attrs = attrs;
    cfg.numAttrs = 1;

    cudaLaunchKernelEx(&cfg, comp_main_kernel, V, w, b, gammas, out, N);
}